// round 15
// baseline (speedup 1.0000x reference)
#include <cuda_runtime.h>
#include <cuda_bf16.h>
#include <mma.h>
#include <cstdint>

using namespace nvcuda;

// Problem constants (fixed by the reference)
#define T_DIM 1024
#define B_DIM 256
#define I_DIM 256
#define H_DIM 256
#define M_DIM (T_DIM * B_DIM)

// Scratch: X = inputs @ W_xh + b_h  (fp32, 268 MB)
__device__ float g_X[(size_t)M_DIM * H_DIM];
// Pre-split weights (bf16 hi + lo), [k][n] layout, written once by prep kernel
__device__ __nv_bfloat16 g_Whi[I_DIM * H_DIM];
__device__ __nv_bfloat16 g_Wlo[I_DIM * H_DIM];

// ---------------------------------------------------------------------------
// packed helpers
// ---------------------------------------------------------------------------
__device__ __forceinline__ void ffma2(unsigned long long& d,
                                      unsigned long long a,
                                      unsigned long long b) {
    asm("fma.rn.f32x2 %0, %1, %2, %0;" : "+l"(d) : "l"(a), "l"(b));
}
__device__ __forceinline__ unsigned long long pk2(float lo, float hi) {
    unsigned long long d;
    asm("mov.b64 %0, {%1, %2};" : "=l"(d) : "f"(lo), "f"(hi));
    return d;
}
__device__ __forceinline__ float2 upk2(unsigned long long a) {
    float2 v;
    asm("mov.b64 {%0, %1}, %2;" : "=f"(v.x), "=f"(v.y) : "l"(a));
    return v;
}
__device__ __forceinline__ float hsum2(unsigned long long a) {
    float2 v = upk2(a);
    return v.x + v.y;
}
// bf16x2 (lo=even k, hi=odd k) -> f32x2 (lo, hi): shl + and, pack free
__device__ __forceinline__ unsigned long long bf2f2(uint32_t b) {
    uint32_t lo = b << 16;
    uint32_t hi = b & 0xffff0000u;
    unsigned long long d;
    asm("mov.b64 %0, {%1, %2};" : "=l"(d) : "r"(lo), "r"(hi));
    return d;
}
__device__ __forceinline__ uint32_t f2bf2(float lo, float hi) {
    uint32_t d;
    asm("cvt.rn.bf16x2.f32 %0, %1, %2;" : "=r"(d) : "f"(hi), "f"(lo));
    return d;
}
__device__ __forceinline__ float fast_tanh(float x) {
    float e, r;
    asm("ex2.approx.f32 %0, %1;" : "=f"(e) : "f"(x * 2.8853900817779268f));
    asm("rcp.approx.f32 %0, %1;" : "=f"(r) : "f"(e + 1.0f));
    return (e - 1.0f) * r;
}

// split 16 consecutive fp32 -> 8 bf16x2 hi + 8 bf16x2 lo, written as 2+2 uint4
__device__ __forceinline__ void split16(const float* v, uint4* hiOut, uint4* loOut) {
    uint32_t h[8], l[8];
#pragma unroll
    for (int j = 0; j < 8; j++) {
        float a0 = v[2 * j], a1 = v[2 * j + 1];
        uint32_t hp = f2bf2(a0, a1);
        float2 hv = upk2(bf2f2(hp));
        l[j] = f2bf2(a0 - hv.x, a1 - hv.y);
        h[j] = hp;
    }
    hiOut[0] = make_uint4(h[0], h[1], h[2], h[3]);
    hiOut[1] = make_uint4(h[4], h[5], h[6], h[7]);
    loOut[0] = make_uint4(l[0], l[1], l[2], l[3]);
    loOut[1] = make_uint4(l[4], l[5], l[6], l[7]);
}

// ---------------------------------------------------------------------------
// Kernel 0: one-time hi/lo split of W_xh ([k][n] layout kept). 64x256 thr.
// ---------------------------------------------------------------------------
__global__ __launch_bounds__(256) void prep_w(const float* __restrict__ W) {
    int i = blockIdx.x * 256 + threadIdx.x;     // 0..16383
    float4 w = *(const float4*)&W[i * 4];
    uint32_t h0 = f2bf2(w.x, w.y), h1 = f2bf2(w.z, w.w);
    float2 v0 = upk2(bf2f2(h0)), v1 = upk2(bf2f2(h1));
    uint32_t l0 = f2bf2(w.x - v0.x, w.y - v0.y);
    uint32_t l1 = f2bf2(w.z - v1.x, w.w - v1.y);
    ((uint2*)g_Whi)[i] = make_uint2(h0, h1);
    ((uint2*)g_Wlo)[i] = make_uint2(l0, l1);
}

// ---------------------------------------------------------------------------
// Kernel 1: X = inputs @ W_xh + b_h — EXACT round-14 wmma GEMM (measured 554us,
// at the HMMA roofline for the 3-term split).
// ---------------------------------------------------------------------------
#define GBM 128
#define GBN 64
#define GBK 32
#define NCHUNK (I_DIM / GBK)   // 8
#define ALD 48
#define BLD 72

#define OFF_BHI 0
#define OFF_BLO (I_DIM * BLD * 2)
#define OFF_A   (2 * I_DIM * BLD * 2)
#define A_COMP  (GBM * ALD * 2)
#define G_SMEM  (OFF_A + 2 * A_COMP)       // 98304

__global__ __launch_bounds__(256, 2) void gemm_xh_tc(
    const float* __restrict__ A,
    const float* __restrict__ bias)
{
    extern __shared__ char gsm[];
    __nv_bfloat16* sBhi = (__nv_bfloat16*)(gsm + OFF_BHI);
    __nv_bfloat16* sBlo = (__nv_bfloat16*)(gsm + OFF_BLO);
    __nv_bfloat16* sAhi = (__nv_bfloat16*)(gsm + OFF_A);
    __nv_bfloat16* sAlo = (__nv_bfloat16*)(gsm + OFF_A + A_COMP);

    const int mTile = blockIdx.x;
    const int nTile = blockIdx.y;
    const int tid = threadIdx.x;
    const int wid = tid >> 5;
    const int wm = wid & 3;
    const int wn = wid >> 2;

    const int aRow = tid >> 1;
    const int aCol = (tid & 1) * 16;
    const float* Ag = A + (size_t)mTile * GBM * I_DIM;

    float* sBiasF = (float*)(gsm + OFF_A);
    for (int idx = tid; idx < 16 * GBN; idx += 256) {
        int r = idx >> 6, c = idx & 63;
        sBiasF[r * BLD + c] = bias[nTile * GBN + c];
    }
    __syncthreads();
    wmma::fragment<wmma::accumulator, 16, 16, 16, float> acc[2][2];
#pragma unroll
    for (int i = 0; i < 2; i++)
#pragma unroll
        for (int j = 0; j < 2; j++)
            wmma::load_matrix_sync(acc[i][j], &sBiasF[wn * 32 + j * 16], BLD,
                                   wmma::mem_row_major);

    {
        const uint4* gh = (const uint4*)g_Whi;
        const uint4* gl = (const uint4*)g_Wlo;
        const int cbase = nTile * 8;
#pragma unroll
        for (int idx = tid; idx < 2048; idx += 256) {
            int row = idx >> 3;
            int q = idx & 7;
            uint4 vh = gh[row * 32 + cbase + q];
            uint4 vl = gl[row * 32 + cbase + q];
            *(uint4*)&sBhi[row * BLD + q * 8] = vh;
            *(uint4*)&sBlo[row * BLD + q * 8] = vl;
        }
    }

    float av[16];
    *(float4*)&av[0]  = *(const float4*)&Ag[(size_t)aRow * I_DIM + aCol + 0];
    *(float4*)&av[4]  = *(const float4*)&Ag[(size_t)aRow * I_DIM + aCol + 4];
    *(float4*)&av[8]  = *(const float4*)&Ag[(size_t)aRow * I_DIM + aCol + 8];
    *(float4*)&av[12] = *(const float4*)&Ag[(size_t)aRow * I_DIM + aCol + 12];

    __syncthreads();

#pragma unroll 1
    for (int ck = 0; ck < NCHUNK; ck++) {
        split16(av, (uint4*)&sAhi[aRow * ALD + aCol],
                    (uint4*)&sAlo[aRow * ALD + aCol]);

        if (ck + 1 < NCHUNK) {
            int k0 = (ck + 1) * GBK;
            *(float4*)&av[0]  = *(const float4*)&Ag[(size_t)aRow * I_DIM + k0 + aCol + 0];
            *(float4*)&av[4]  = *(const float4*)&Ag[(size_t)aRow * I_DIM + k0 + aCol + 4];
            *(float4*)&av[8]  = *(const float4*)&Ag[(size_t)aRow * I_DIM + k0 + aCol + 8];
            *(float4*)&av[12] = *(const float4*)&Ag[(size_t)aRow * I_DIM + k0 + aCol + 12];
        }

        __syncthreads();

#pragma unroll
        for (int ks = 0; ks < 2; ks++) {
            const int kg = ck * GBK + ks * 16;
            wmma::fragment<wmma::matrix_a, 16, 16, 16, __nv_bfloat16, wmma::row_major> afh[2], afl[2];
            wmma::fragment<wmma::matrix_b, 16, 16, 16, __nv_bfloat16, wmma::row_major> bfh[2], bfl[2];
#pragma unroll
            for (int i = 0; i < 2; i++) {
                wmma::load_matrix_sync(afh[i], &sAhi[(wm * 32 + i * 16) * ALD + ks * 16], ALD);
                wmma::load_matrix_sync(afl[i], &sAlo[(wm * 32 + i * 16) * ALD + ks * 16], ALD);
            }
#pragma unroll
            for (int j = 0; j < 2; j++) {
                wmma::load_matrix_sync(bfh[j], &sBhi[kg * BLD + wn * 32 + j * 16], BLD);
                wmma::load_matrix_sync(bfl[j], &sBlo[kg * BLD + wn * 32 + j * 16], BLD);
            }
#pragma unroll
            for (int i = 0; i < 2; i++)
#pragma unroll
                for (int j = 0; j < 2; j++) {
                    wmma::mma_sync(acc[i][j], afh[i], bfh[j], acc[i][j]);
                    wmma::mma_sync(acc[i][j], afh[i], bfl[j], acc[i][j]);
                    wmma::mma_sync(acc[i][j], afl[i], bfh[j], acc[i][j]);
                }
        }

        __syncthreads();
    }

#pragma unroll
    for (int i = 0; i < 2; i++)
#pragma unroll
        for (int j = 0; j < 2; j++) {
            size_t row0 = (size_t)mTile * GBM + wm * 32 + i * 16;
            int col0 = nTile * GBN + wn * 32 + j * 16;
            wmma::store_matrix_sync(&g_X[row0 * H_DIM + col0], acc[i][j], H_DIM,
                                    wmma::mem_row_major);
        }
}

// ---------------------------------------------------------------------------
// Kernel 2: the recurrence — ALL weights as bf16x2 IN REGISTERS (64 u32/thr;
// 512 thr x 64 = 32K regs). No weight LDS at all; per step each u32 is
// decompressed with shl/and (alu pipe) feeding f32x2 FMAs (fma pipe) — the
// two pipes run concurrently. State stays in smem (broadcast reads, skewed,
// double-buffered, one barrier per step). Same reduce-scatter epilogue.
// ---------------------------------------------------------------------------
#define SROW 272
#define BUF_F (2 * SROW)

__global__ __launch_bounds__(512, 1) void rnn_kernel(
    const float* __restrict__ W,
    float* __restrict__ out,
    int write_state)
{
    __shared__ float S0[BUF_F];
    __shared__ float S1[BUF_F];

    const int tid = threadIdx.x;
    const int wid = tid >> 5;
    const int lane = tid & 31;
    const int p = wid * 8 + (lane & 7);     // column pair 0..127
    const int s = lane >> 3;                // k-split 0..3
    const int h0 = 2 * p;
    const int kbase = 64 * s;
    const int bidx0 = blockIdx.x * 2;
    const int hs = h0 + ((h0 >> 6) << 2);   // skewed state index
    const bool sb0 = (s & 1);
    const int sb1 = (s >> 1);

    // ALL weights in registers as bf16x2: pair j covers k = kbase+2j, +2j+1
    uint32_t rwA[32], rwB[32];
#pragma unroll
    for (int j = 0; j < 32; j++) {
        int k = kbase + 2 * j;
        float2 wk  = *(const float2*)&W[(size_t)k * H_DIM + h0];
        float2 wk1 = *(const float2*)&W[(size_t)(k + 1) * H_DIM + h0];
        rwA[j] = f2bf2(wk.x, wk1.x);
        rwB[j] = f2bf2(wk.y, wk1.y);
    }

    // zero both state buffers (incl. pads)
    for (int i = tid; i < BUF_F; i += 512) { S0[i] = 0.0f; S1[i] = 0.0f; }
    __syncthreads();

    const int stoff = sb1 * SROW + hs + (sb0 ? 1 : 0);
    const size_t goff = (size_t)(bidx0 + sb1) * H_DIM + h0 + (sb0 ? 1 : 0);
    float* outp = out + goff;
    const float* xp = g_X + goff;
    float* state_out = out + (size_t)T_DIM * B_DIM * H_DIM + goff;

    float x_nxt = *xp;   // x(t=0)

    auto step = [&](int t, const float* Sr, float* Sw) {
        const ulonglong2* su0 = (const ulonglong2*)(Sr + 68 * s);          // row 0
        const ulonglong2* su1 = (const ulonglong2*)(Sr + SROW + 68 * s);   // row 1

        float x_cur = x_nxt;
        int tn = (t + 1 < T_DIM) ? (t + 1) : t;
        x_nxt = xp[(size_t)tn * (B_DIM * H_DIM)];

        unsigned long long a00 = 0ull, a01 = 0ull, a10 = 0ull, a11 = 0ull;

#pragma unroll
        for (int j = 0; j < 16; j++) {
            ulonglong2 s0 = su0[j];
            ulonglong2 s1 = su1[j];
            // pairs 2j (s.x) and 2j+1 (s.y); decompress once, use for both rows
            unsigned long long wA0 = bf2f2(rwA[2 * j]);
            unsigned long long wB0 = bf2f2(rwB[2 * j]);
            unsigned long long wA1 = bf2f2(rwA[2 * j + 1]);
            unsigned long long wB1 = bf2f2(rwB[2 * j + 1]);
            ffma2(a00, s0.x, wA0); ffma2(a01, s0.x, wB0);
            ffma2(a00, s0.y, wA1); ffma2(a01, s0.y, wB1);
            ffma2(a10, s1.x, wA0); ffma2(a11, s1.x, wB0);
            ffma2(a10, s1.y, wA1); ffma2(a11, s1.y, wB1);
        }

        float f00 = hsum2(a00), f01 = hsum2(a01);
        float f10 = hsum2(a10), f11 = hsum2(a11);

        // 2-level reduce-scatter over the 4 k-splits (3 scalar SHFLs)
        float m0 = sb0 ? f01 : f00;
        float m1 = sb0 ? f11 : f10;
        float o0 = sb0 ? f00 : f01;
        float o1 = sb0 ? f10 : f11;
        m0 += __shfl_xor_sync(0xffffffffu, o0, 8);
        m1 += __shfl_xor_sync(0xffffffffu, o1, 8);
        float mm = sb1 ? m1 : m0;
        float oo = sb1 ? m0 : m1;
        mm += __shfl_xor_sync(0xffffffffu, oo, 16);

        float h = fast_tanh(mm + x_cur);

        Sw[stoff] = h;
        outp[(size_t)t * (B_DIM * H_DIM)] = h;

        __syncthreads();
    };

#pragma unroll 1
    for (int t = 0; t < T_DIM; t += 2) {
        step(t,     S0, S1);
        step(t + 1, S1, S0);
    }

    if (write_state) *state_out = S0[stoff];
}

// ---------------------------------------------------------------------------
// Launch
// ---------------------------------------------------------------------------
extern "C" void kernel_launch(void* const* d_in, const int* in_sizes, int n_in,
                              void* d_out, int out_size)
{
    (void)n_in; (void)in_sizes;
    const float* inputs = (const float*)d_in[0];  // [T,B,I]
    const float* W_xh   = (const float*)d_in[1];  // [I,H]
    const float* W_hh   = (const float*)d_in[2];  // [H,H]
    const float* b_h    = (const float*)d_in[3];  // [H]
    float* out = (float*)d_out;

    const long long need = (long long)T_DIM * B_DIM * H_DIM + (long long)B_DIM * H_DIM;
    int write_state = ((long long)out_size >= need) ? 1 : 0;

    prep_w<<<64, 256>>>(W_xh);

    cudaFuncSetAttribute(gemm_xh_tc, cudaFuncAttributeMaxDynamicSharedMemorySize,
                         G_SMEM);
    dim3 g1(M_DIM / GBM, H_DIM / GBN);
    gemm_xh_tc<<<g1, 256, G_SMEM>>>(inputs, b_h);

    rnn_kernel<<<B_DIM / 2, 512>>>(W_hh, out, write_state);
}

// round 17
// speedup vs baseline: 1.6627x; 1.6627x over previous
#include <cuda_runtime.h>
#include <cuda_bf16.h>
#include <mma.h>
#include <cstdint>

using namespace nvcuda;

// Problem constants (fixed by the reference)
#define T_DIM 1024
#define B_DIM 256
#define I_DIM 256
#define H_DIM 256
#define M_DIM (T_DIM * B_DIM)

// Scratch: X = inputs @ W_xh + b_h  (fp32, 268 MB)
__device__ float g_X[(size_t)M_DIM * H_DIM];
// Pre-split weights (bf16 hi + lo), [k][n] layout, written once by prep kernel
__device__ __nv_bfloat16 g_Whi[I_DIM * H_DIM];
__device__ __nv_bfloat16 g_Wlo[I_DIM * H_DIM];

// ---------------------------------------------------------------------------
// packed helpers
// ---------------------------------------------------------------------------
__device__ __forceinline__ void ffma2(unsigned long long& d,
                                      unsigned long long a,
                                      unsigned long long b) {
    asm("fma.rn.f32x2 %0, %1, %2, %0;" : "+l"(d) : "l"(a), "l"(b));
}
__device__ __forceinline__ unsigned long long pk2(float lo, float hi) {
    unsigned long long d;
    asm("mov.b64 %0, {%1, %2};" : "=l"(d) : "f"(lo), "f"(hi));
    return d;
}
__device__ __forceinline__ float2 upk2(unsigned long long a) {
    float2 v;
    asm("mov.b64 {%0, %1}, %2;" : "=f"(v.x), "=f"(v.y) : "l"(a));
    return v;
}
__device__ __forceinline__ float hsum2(unsigned long long a) {
    float2 v = upk2(a);
    return v.x + v.y;
}
__device__ __forceinline__ unsigned long long bf2f2(uint32_t b) {
    uint32_t lo = b << 16;
    uint32_t hi = b & 0xffff0000u;
    unsigned long long d;
    asm("mov.b64 %0, {%1, %2};" : "=l"(d) : "r"(lo), "r"(hi));
    return d;
}
__device__ __forceinline__ uint32_t f2bf2(float lo, float hi) {
    uint32_t d;
    asm("cvt.rn.bf16x2.f32 %0, %1, %2;" : "=r"(d) : "f"(hi), "f"(lo));
    return d;
}
__device__ __forceinline__ float fast_tanh(float x) {
    float e, r;
    asm("ex2.approx.f32 %0, %1;" : "=f"(e) : "f"(x * 2.8853900817779268f));
    asm("rcp.approx.f32 %0, %1;" : "=f"(r) : "f"(e + 1.0f));
    return (e - 1.0f) * r;
}

// split 8 consecutive fp32 -> 4 bf16x2 hi + 4 bf16x2 lo (one uint4 each)
__device__ __forceinline__ void split8(const float* v, uint4* hiOut, uint4* loOut) {
    uint32_t h[4], l[4];
#pragma unroll
    for (int j = 0; j < 4; j++) {
        float a0 = v[2 * j], a1 = v[2 * j + 1];
        uint32_t hp = f2bf2(a0, a1);
        float2 hv = upk2(bf2f2(hp));
        l[j] = f2bf2(a0 - hv.x, a1 - hv.y);
        h[j] = hp;
    }
    hiOut[0] = make_uint4(h[0], h[1], h[2], h[3]);
    loOut[0] = make_uint4(l[0], l[1], l[2], l[3]);
}

// ---------------------------------------------------------------------------
// Kernel 0: one-time hi/lo split of W_xh ([k][n] layout kept). 64x256 thr.
// ---------------------------------------------------------------------------
__global__ __launch_bounds__(256) void prep_w(const float* __restrict__ W) {
    int i = blockIdx.x * 256 + threadIdx.x;     // 0..16383
    float4 w = *(const float4*)&W[i * 4];
    uint32_t h0 = f2bf2(w.x, w.y), h1 = f2bf2(w.z, w.w);
    float2 v0 = upk2(bf2f2(h0)), v1 = upk2(bf2f2(h1));
    uint32_t l0 = f2bf2(w.x - v0.x, w.y - v0.y);
    uint32_t l1 = f2bf2(w.z - v1.x, w.w - v1.y);
    ((uint2*)g_Whi)[i] = make_uint2(h0, h1);
    ((uint2*)g_Wlo)[i] = make_uint2(l0, l1);
}

// ---------------------------------------------------------------------------
// Kernel 1: X = inputs @ W_xh + b_h — wmma bf16 3-term split
// (X ~= Ahi*Whi + Ahi*Wlo + Alo*Whi), DOUBLE-BUFFERED A with prefetch
// distance 2: GBK=16, one barrier per chunk, LDG->consume distance ~2 compute
// phases (> DRAM 577cyc). B slice (256x64 hi+lo) resident. 2 CTAs/SM.
// ---------------------------------------------------------------------------
#define GBM 128
#define GBN 64
#define GBK 16
#define NCHUNK (I_DIM / GBK)   // 16
#define ALD 24                 // A leading dim bf16 (16 data + 8 pad) = 48B rows
#define BLD 72                 // B leading dim bf16 (64 data + 8 pad)

#define OFF_BHI 0
#define OFF_BLO (I_DIM * BLD * 2)          // 36864
#define OFF_A   (2 * I_DIM * BLD * 2)      // 73728
#define A_HALF  (GBM * ALD * 2)            // 6144 bytes (hi or lo, one buffer)
#define A_BUF   (2 * A_HALF)               // 12288 per buffer (hi+lo)
#define G_SMEM  (OFF_A + 2 * A_BUF)        // 98304

__global__ __launch_bounds__(256, 2) void gemm_xh_tc(
    const float* __restrict__ A,     // [M_DIM, I_DIM]
    const float* __restrict__ bias)  // [H_DIM]
{
    extern __shared__ char gsm[];
    __nv_bfloat16* sBhi = (__nv_bfloat16*)(gsm + OFF_BHI);   // [256][BLD]
    __nv_bfloat16* sBlo = (__nv_bfloat16*)(gsm + OFF_BLO);   // [256][BLD]
    // A buffers: buf b hi at OFF_A + b*A_BUF, lo at +A_HALF
    __nv_bfloat16* sAhi[2] = {(__nv_bfloat16*)(gsm + OFF_A),
                              (__nv_bfloat16*)(gsm + OFF_A + A_BUF)};
    __nv_bfloat16* sAlo[2] = {(__nv_bfloat16*)(gsm + OFF_A + A_HALF),
                              (__nv_bfloat16*)(gsm + OFF_A + A_BUF + A_HALF)};

    const int mTile = blockIdx.x;
    const int nTile = blockIdx.y;
    const int tid = threadIdx.x;
    const int wid = tid >> 5;
    const int wm = wid & 3;          // 32-row block
    const int wn = wid >> 2;         // 32-col block

    // A tile: 128 rows x 16 k; thread loads 8 floats
    const int aRow = tid >> 1;
    const int aCol = (tid & 1) * 8;
    const float* Ag = A + (size_t)mTile * GBM * I_DIM;

    // ---- bias -> accumulators (staged in the A region)
    float* sBiasF = (float*)(gsm + OFF_A);
    for (int idx = tid; idx < 16 * GBN; idx += 256) {
        int r = idx >> 6, c = idx & 63;
        sBiasF[r * BLD + c] = bias[nTile * GBN + c];
    }
    __syncthreads();
    wmma::fragment<wmma::accumulator, 16, 16, 16, float> acc[2][2];
#pragma unroll
    for (int i = 0; i < 2; i++)
#pragma unroll
        for (int j = 0; j < 2; j++)
            wmma::load_matrix_sync(acc[i][j], &sBiasF[wn * 32 + j * 16], BLD,
                                   wmma::mem_row_major);

    // ---- load resident B slice (hi+lo): 256 k-rows x 64 cols
    {
        const uint4* gh = (const uint4*)g_Whi;   // row stride 32 uint4
        const uint4* gl = (const uint4*)g_Wlo;
        const int cbase = nTile * 8;
#pragma unroll
        for (int idx = tid; idx < 2048; idx += 256) {
            int row = idx >> 3;
            int q = idx & 7;
            uint4 vh = gh[row * 32 + cbase + q];
            uint4 vl = gl[row * 32 + cbase + q];
            *(uint4*)&sBhi[row * BLD + q * 8] = vh;
            *(uint4*)&sBlo[row * BLD + q * 8] = vl;
        }
    }

    // preload chunks 0 and 1 into the two register sets
    float av[2][8];
#pragma unroll
    for (int c = 0; c < 2; c++) {
        *(float4*)&av[c][0] = *(const float4*)&Ag[(size_t)aRow * I_DIM + c * GBK + aCol + 0];
        *(float4*)&av[c][4] = *(const float4*)&Ag[(size_t)aRow * I_DIM + c * GBK + aCol + 4];
    }
    __syncthreads();   // bias reads + B stores complete

    // split chunk 0 into buffer 0
    split8(av[0], (uint4*)&sAhi[0][aRow * ALD + aCol],
                  (uint4*)&sAlo[0][aRow * ALD + aCol]);
    __syncthreads();

#pragma unroll 2
    for (int ck = 0; ck < NCHUNK; ck++) {
        const int cur = ck & 1;

        // 1) issue LDG for chunk ck+2 into register set cur (old content consumed)
        if (ck + 2 < NCHUNK) {
            int k0 = (ck + 2) * GBK;
            *(float4*)&av[cur][0] = *(const float4*)&Ag[(size_t)aRow * I_DIM + k0 + aCol + 0];
            *(float4*)&av[cur][4] = *(const float4*)&Ag[(size_t)aRow * I_DIM + k0 + aCol + 4];
        }

        // 2) compute chunk ck from buf[cur]
        {
            const int kg = ck * GBK;
            wmma::fragment<wmma::matrix_a, 16, 16, 16, __nv_bfloat16, wmma::row_major> afh[2], afl[2];
            wmma::fragment<wmma::matrix_b, 16, 16, 16, __nv_bfloat16, wmma::row_major> bfh[2], bfl[2];
#pragma unroll
            for (int i = 0; i < 2; i++) {
                wmma::load_matrix_sync(afh[i], &sAhi[cur][(wm * 32 + i * 16) * ALD], ALD);
                wmma::load_matrix_sync(afl[i], &sAlo[cur][(wm * 32 + i * 16) * ALD], ALD);
            }
#pragma unroll
            for (int j = 0; j < 2; j++) {
                wmma::load_matrix_sync(bfh[j], &sBhi[kg * BLD + wn * 32 + j * 16], BLD);
                wmma::load_matrix_sync(bfl[j], &sBlo[kg * BLD + wn * 32 + j * 16], BLD);
            }
#pragma unroll
            for (int i = 0; i < 2; i++)
#pragma unroll
                for (int j = 0; j < 2; j++) {
                    wmma::mma_sync(acc[i][j], afh[i], bfh[j], acc[i][j]);
                    wmma::mma_sync(acc[i][j], afh[i], bfl[j], acc[i][j]);
                    wmma::mma_sync(acc[i][j], afl[i], bfh[j], acc[i][j]);
                }
        }

        // 3) split chunk ck+1 into buf[cur^1] (its readers finished at the
        //    barrier ending iteration ck-1), then 4) one barrier
        if (ck + 1 < NCHUNK) {
            split8(av[cur ^ 1], (uint4*)&sAhi[cur ^ 1][aRow * ALD + aCol],
                                (uint4*)&sAlo[cur ^ 1][aRow * ALD + aCol]);
            __syncthreads();
        }
    }

    // store accumulators (bias already folded in)
#pragma unroll
    for (int i = 0; i < 2; i++)
#pragma unroll
        for (int j = 0; j < 2; j++) {
            size_t row0 = (size_t)mTile * GBM + wm * 32 + i * 16;
            int col0 = nTile * GBN + wn * 32 + j * 16;
            wmma::store_matrix_sync(&g_X[row0 * H_DIM + col0], acc[i][j], H_DIM,
                                    wmma::mem_row_major);
        }
}

// ---------------------------------------------------------------------------
// Kernel 2: the recurrence — EXACT round-8 version (measured ~1088us).
// ---------------------------------------------------------------------------
#define SROW 272
#define BUF_F (2 * SROW)
#define PAIR_STRIDE_U32 36
#define SPLIT_STRIDE_U32 (128 * PAIR_STRIDE_U32 + 4)
#define SMEM_STATE_F (2 * BUF_F)
#define RNN_SMEM_F (SMEM_STATE_F + 4 * SPLIT_STRIDE_U32)
#define RNN_SMEM_B (RNN_SMEM_F * 4)

__global__ __launch_bounds__(512, 1) void rnn_kernel(
    const float* __restrict__ W,
    float* __restrict__ out,
    int write_state)
{
    extern __shared__ float sm[];
    float* S0 = sm;
    float* S1 = sm + BUF_F;
    uint32_t* WB = (uint32_t*)(sm + SMEM_STATE_F);

    const int tid = threadIdx.x;
    const int wid = tid >> 5;
    const int lane = tid & 31;
    const int p = wid * 8 + (lane & 7);
    const int s = lane >> 3;
    const int h0 = 2 * p;
    const int kbase = 64 * s;
    const int bidx0 = blockIdx.x * 2;
    const int hs = h0 + ((h0 >> 6) << 2);
    const bool sb0 = (s & 1);
    const int sb1 = (s >> 1);

    unsigned long long wrA[16], wrB[16];
#pragma unroll
    for (int j = 0; j < 16; j++) {
        int k = kbase + 2 * j;
        float2 wk  = *(const float2*)&W[(size_t)k * H_DIM + h0];
        float2 wk1 = *(const float2*)&W[(size_t)(k + 1) * H_DIM + h0];
        wrA[j] = pk2(wk.x, wk1.x);
        wrB[j] = pk2(wk.y, wk1.y);
    }

    uint32_t* myWB = WB + s * SPLIT_STRIDE_U32 + p * PAIR_STRIDE_U32;
#pragma unroll
    for (int j = 0; j < 16; j++) {
        int k = kbase + 32 + 2 * j;
        float2 wk  = *(const float2*)&W[(size_t)k * H_DIM + h0];
        float2 wk1 = *(const float2*)&W[(size_t)(k + 1) * H_DIM + h0];
        myWB[2 * j]     = f2bf2(wk.x, wk1.x);
        myWB[2 * j + 1] = f2bf2(wk.y, wk1.y);
    }

    for (int i = tid; i < SMEM_STATE_F; i += 512) sm[i] = 0.0f;
    __syncthreads();

    const uint4* wq = (const uint4*)myWB;
    const int stoff = sb1 * SROW + hs + (sb0 ? 1 : 0);
    const size_t goff = (size_t)(bidx0 + sb1) * H_DIM + h0 + (sb0 ? 1 : 0);
    float* outp = out + goff;
    const float* xp = g_X + goff;
    float* state_out = out + (size_t)T_DIM * B_DIM * H_DIM + goff;

    float x_nxt = *xp;

    auto step = [&](int t, const float* Sr, float* Sw) {
        const ulonglong2* su0 = (const ulonglong2*)(Sr + 68 * s);
        const ulonglong2* su1 = (const ulonglong2*)(Sr + SROW + 68 * s);

        float x_cur = x_nxt;
        int tn = (t + 1 < T_DIM) ? (t + 1) : t;
        x_nxt = xp[(size_t)tn * (B_DIM * H_DIM)];

        unsigned long long a00 = 0ull, a01 = 0ull, a10 = 0ull, a11 = 0ull;

#pragma unroll
        for (int j2 = 0; j2 < 8; j2++) {
            ulonglong2 s0 = su0[j2];
            ulonglong2 s1 = su1[j2];
            ffma2(a00, s0.x, wrA[2 * j2]);     ffma2(a01, s0.x, wrB[2 * j2]);
            ffma2(a00, s0.y, wrA[2 * j2 + 1]); ffma2(a01, s0.y, wrB[2 * j2 + 1]);
            ffma2(a10, s1.x, wrA[2 * j2]);     ffma2(a11, s1.x, wrB[2 * j2]);
            ffma2(a10, s1.y, wrA[2 * j2 + 1]); ffma2(a11, s1.y, wrB[2 * j2 + 1]);
        }
#pragma unroll
        for (int j2 = 0; j2 < 8; j2++) {
            uint4 q = wq[j2];
            unsigned long long wA0 = bf2f2(q.x);
            unsigned long long wB0 = bf2f2(q.y);
            unsigned long long wA1 = bf2f2(q.z);
            unsigned long long wB1 = bf2f2(q.w);
            ulonglong2 s0 = su0[8 + j2];
            ulonglong2 s1 = su1[8 + j2];
            ffma2(a00, s0.x, wA0); ffma2(a01, s0.x, wB0);
            ffma2(a00, s0.y, wA1); ffma2(a01, s0.y, wB1);
            ffma2(a10, s1.x, wA0); ffma2(a11, s1.x, wB0);
            ffma2(a10, s1.y, wA1); ffma2(a11, s1.y, wB1);
        }

        float f00 = hsum2(a00), f01 = hsum2(a01);
        float f10 = hsum2(a10), f11 = hsum2(a11);

        float m0 = sb0 ? f01 : f00;
        float m1 = sb0 ? f11 : f10;
        float o0 = sb0 ? f00 : f01;
        float o1 = sb0 ? f10 : f11;
        m0 += __shfl_xor_sync(0xffffffffu, o0, 8);
        m1 += __shfl_xor_sync(0xffffffffu, o1, 8);
        float mm = sb1 ? m1 : m0;
        float oo = sb1 ? m0 : m1;
        mm += __shfl_xor_sync(0xffffffffu, oo, 16);

        float h = fast_tanh(mm + x_cur);

        Sw[stoff] = h;
        outp[(size_t)t * (B_DIM * H_DIM)] = h;

        __syncthreads();
    };

#pragma unroll 1
    for (int t = 0; t < T_DIM; t += 2) {
        step(t,     S0, S1);
        step(t + 1, S1, S0);
    }

    if (write_state) *state_out = S0[stoff];
}

// ---------------------------------------------------------------------------
// Launch
// ---------------------------------------------------------------------------
extern "C" void kernel_launch(void* const* d_in, const int* in_sizes, int n_in,
                              void* d_out, int out_size)
{
    (void)n_in; (void)in_sizes;
    const float* inputs = (const float*)d_in[0];  // [T,B,I]
    const float* W_xh   = (const float*)d_in[1];  // [I,H]
    const float* W_hh   = (const float*)d_in[2];  // [H,H]
    const float* b_h    = (const float*)d_in[3];  // [H]
    float* out = (float*)d_out;

    const long long need = (long long)T_DIM * B_DIM * H_DIM + (long long)B_DIM * H_DIM;
    int write_state = ((long long)out_size >= need) ? 1 : 0;

    prep_w<<<64, 256>>>(W_xh);

    cudaFuncSetAttribute(gemm_xh_tc, cudaFuncAttributeMaxDynamicSharedMemorySize,
                         G_SMEM);
    dim3 g1(M_DIM / GBM, H_DIM / GBN);
    gemm_xh_tc<<<g1, 256, G_SMEM>>>(inputs, b_h);

    cudaFuncSetAttribute(rnn_kernel, cudaFuncAttributeMaxDynamicSharedMemorySize,
                         RNN_SMEM_B);
    rnn_kernel<<<B_DIM / 2, 512, RNN_SMEM_B>>>(W_hh, out, write_state);
}